// round 1
// baseline (speedup 1.0000x reference)
#include <cuda_runtime.h>
#include <cuda_bf16.h>

#define TPB  256
#define TILE 128   // points per block

// Activations stored feature-major: element (feat c, point r) at
//   sA[c*128 + (r ^ (((c>>3)&7)*4))]
// XOR swizzle keeps both the broadcast reads and the strided writebacks
// bank-conflict free, and preserves float4 contiguity (r0 multiple of 4).

__device__ __forceinline__ int aoff(int c, int r) {
    return (c << 7) + (r ^ (((c >> 3) & 7) << 2));
}

__device__ __forceinline__ void stage_w(float* sW, const float* __restrict__ g, int n4, int t) {
    const float4* src = (const float4*)g;
    float4* dst = (float4*)sW;
    for (int i = t; i < n4; i += TPB) dst[i] = src[i];
}

// Load a [N,32] row-major gmem tensor transposed into sA rows 0..31.
__device__ __forceinline__ void load_in32(float* sA, const float* __restrict__ g,
                                          int block0, int t) {
    for (int i = t; i < TILE * 8; i += TPB) {
        int p  = i >> 3;
        int c4 = (i & 7) << 2;
        float4 v = *(const float4*)(g + (size_t)(block0 + p) * 32 + c4);
        // c4..c4+3 share the same (c>>3) so the swizzle constant is identical
        int sw = ((c4 >> 3) & 7) << 2;
        int pr = p ^ sw;
        sA[((c4 + 0) << 7) + pr] = v.x;
        sA[((c4 + 1) << 7) + pr] = v.y;
        sA[((c4 + 2) << 7) + pr] = v.z;
        sA[((c4 + 3) << 7) + pr] = v.w;
    }
}

template <int K, int COUT, int MC>
__device__ __forceinline__ void accum_tile(const float* __restrict__ sA,
                                           const float* __restrict__ sW,
                                           int rg, int cg, float (&acc)[4][MC]) {
#pragma unroll
    for (int i = 0; i < 4; i++)
#pragma unroll
        for (int j = 0; j < MC; j++) acc[i][j] = 0.f;

    const int r0 = rg << 2;
#pragma unroll 8
    for (int k = 0; k < K; k++) {
        float4 a = *(const float4*)(sA + (k << 7) + (r0 ^ (((k >> 3) & 7) << 2)));
        float w[MC];
        if constexpr (MC == 8) {
            float4 w0 = *(const float4*)(sW + k * COUT + (cg << 3));
            float4 w1 = *(const float4*)(sW + k * COUT + (cg << 3) + 4);
            w[0] = w0.x; w[1] = w0.y; w[2] = w0.z; w[3] = w0.w;
            w[4] = w1.x; w[5] = w1.y; w[6] = w1.z; w[7] = w1.w;
        } else {
            float2 w0 = *(const float2*)(sW + k * COUT + cg * MC);
            w[0] = w0.x; w[1] = w0.y;
        }
        float av[4] = {a.x, a.y, a.z, a.w};
#pragma unroll
        for (int i = 0; i < 4; i++)
#pragma unroll
            for (int j = 0; j < MC; j++)
                acc[i][j] = fmaf(av[i], w[j], acc[i][j]);
    }
}

template <int MC>
__device__ __forceinline__ void writeback_relu(float* sA, int rg, int cg,
                                               float (&acc)[4][MC]) {
    const int r0 = rg << 2;
#pragma unroll
    for (int j = 0; j < MC; j++) {
        int c = cg * MC + j;
        float4 v = make_float4(fmaxf(acc[0][j], 0.f), fmaxf(acc[1][j], 0.f),
                               fmaxf(acc[2][j], 0.f), fmaxf(acc[3][j], 0.f));
        *(float4*)(sA + aoff(c, r0)) = v;
    }
}

__global__ __launch_bounds__(TPB)
void RadianceFieldGrid_kernel(const float* __restrict__ x,
                              const float* __restrict__ d,
                              const float* __restrict__ Ws0,
                              const float* __restrict__ Ws1,
                              const float* __restrict__ Ws2,
                              const float* __restrict__ Wc0,
                              const float* __restrict__ Wc1,
                              const float* __restrict__ Wc2,
                              const float* __restrict__ Wc3,
                              float* __restrict__ out, int N) {
    __shared__ float sA[64 * 128];   // 32 KB activations, feature-major swizzled
    __shared__ float sW[64 * 64];    // 16 KB current-layer weights [k][c]

    const int t      = threadIdx.x;
    const int block0 = blockIdx.x * TILE;
    const int rg     = t >> 3;       // 0..31  -> rows rg*4..rg*4+3
    const int cg     = t & 7;        // 0..7   -> cols cg*MC..

    // ---- stage x (rows 0..31) + Ws0 ----
    load_in32(sA, x, block0, t);
    stage_w(sW, Ws0, 32 * 64 / 4, t);
    __syncthreads();

    // ---- sigma layer 0: 32 -> 64, relu ----
    {
        float acc[4][8];
        accum_tile<32, 64, 8>(sA, sW, rg, cg, acc);
        __syncthreads();
        writeback_relu<8>(sA, rg, cg, acc);
        stage_w(sW, Ws1, 64 * 64 / 4, t);
        __syncthreads();
    }

    // ---- sigma layer 1: 64 -> 64, relu ----
    {
        float acc[4][8];
        accum_tile<64, 64, 8>(sA, sW, rg, cg, acc);
        __syncthreads();
        writeback_relu<8>(sA, rg, cg, acc);
        stage_w(sW, Ws2, 64 * 16 / 4, t);
        __syncthreads();
    }

    // ---- sigma layer 2: 64 -> 16, relu. col 0 = sigma -> gmem, cols 1..15 = geo -> rows 32..46 ----
    {
        float acc[4][2];
        accum_tile<64, 16, 2>(sA, sW, rg, cg, acc);
        __syncthreads();
        const int r0 = rg << 2;
#pragma unroll
        for (int j = 0; j < 2; j++) {
            int c = cg * 2 + j;
            float4 v = make_float4(fmaxf(acc[0][j], 0.f), fmaxf(acc[1][j], 0.f),
                                   fmaxf(acc[2][j], 0.f), fmaxf(acc[3][j], 0.f));
            if (c == 0) {
                // sigma output region: out[3N + point]
                *(float4*)(out + (size_t)3 * N + block0 + r0) = v;
            } else {
                int row = 31 + c;  // geo feature c-1 -> concat slot 32+(c-1)
                *(float4*)(sA + aoff(row, r0)) = v;
            }
        }
        // d into rows 0..31 (overwrites old activations; accumulate is done)
        load_in32(sA, d, block0, t);
        stage_w(sW, Wc0, 47 * 64 / 4, t);
        __syncthreads();
    }

    // ---- color layer 0: 47 -> 64, relu ----
    {
        float acc[4][8];
        accum_tile<47, 64, 8>(sA, sW, rg, cg, acc);
        __syncthreads();
        writeback_relu<8>(sA, rg, cg, acc);
        stage_w(sW, Wc1, 64 * 64 / 4, t);
        __syncthreads();
    }

    // ---- color layer 1: 64 -> 64, relu ----
    {
        float acc[4][8];
        accum_tile<64, 64, 8>(sA, sW, rg, cg, acc);
        __syncthreads();
        writeback_relu<8>(sA, rg, cg, acc);
        stage_w(sW, Wc2, 64 * 64 / 4, t);
        __syncthreads();
    }

    // ---- color layer 2: 64 -> 64, relu ----
    {
        float acc[4][8];
        accum_tile<64, 64, 8>(sA, sW, rg, cg, acc);
        __syncthreads();
        writeback_relu<8>(sA, rg, cg, acc);
        stage_w(sW, Wc3, 64 * 3 / 4, t);
        __syncthreads();
    }

    // ---- color layer 3: 64 -> 3, sigmoid, store ----
    if (t < TILE) {
        float c0 = 0.f, c1 = 0.f, c2 = 0.f;
#pragma unroll 8
        for (int k = 0; k < 64; k++) {
            float a = sA[(k << 7) + (t ^ (((k >> 3) & 7) << 2))];
            c0 = fmaf(a, sW[k * 3 + 0], c0);
            c1 = fmaf(a, sW[k * 3 + 1], c1);
            c2 = fmaf(a, sW[k * 3 + 2], c2);
        }
        float* o = out + (size_t)(block0 + t) * 3;
        o[0] = 1.f / (1.f + expf(-c0));
        o[1] = 1.f / (1.f + expf(-c1));
        o[2] = 1.f / (1.f + expf(-c2));
    }
}

extern "C" void kernel_launch(void* const* d_in, const int* in_sizes, int n_in,
                              void* d_out, int out_size) {
    const float* x   = (const float*)d_in[0];
    const float* d   = (const float*)d_in[1];
    const float* Ws0 = (const float*)d_in[2];
    const float* Ws1 = (const float*)d_in[3];
    const float* Ws2 = (const float*)d_in[4];
    const float* Wc0 = (const float*)d_in[5];
    const float* Wc1 = (const float*)d_in[6];
    const float* Wc2 = (const float*)d_in[7];
    const float* Wc3 = (const float*)d_in[8];
    float* out = (float*)d_out;

    int N = in_sizes[0] / 32;           // x is [N, 32]
    int blocks = (N + TILE - 1) / TILE; // N = 2^20 -> 8192 exact
    RadianceFieldGrid_kernel<<<blocks, TPB>>>(x, d, Ws0, Ws1, Ws2,
                                              Wc0, Wc1, Wc2, Wc3, out, N);
}

// round 2
// speedup vs baseline: 2.4058x; 2.4058x over previous
#include <cuda_runtime.h>
#include <cuda_bf16.h>
#include <cstdint>

#define TPB   256
#define PTS   256          // points per CTA (8 warps x 32 points)
#define S     68           // smem row stride (floats); 68 mod 32 == 4 -> conflict-free frags

// smem: sA [256][S] activations (tf32-rounded), sW [64][S] weights transposed [n][k]
#define SA_FLOATS (PTS * S)
#define SW_FLOATS (64 * S)
#define SMEM_BYTES ((SA_FLOATS + SW_FLOATS) * 4)

__device__ __forceinline__ float cvt_tf32(float x) {
    uint32_t u;
    asm("cvt.rna.tf32.f32 %0, %1;" : "=r"(u) : "f"(x));
    return __uint_as_float(u);
}

__device__ __forceinline__ void mma8(float* d, const uint32_t* a, uint32_t b0, uint32_t b1) {
    asm volatile(
        "mma.sync.aligned.m16n8k8.row.col.f32.tf32.tf32.f32 "
        "{%0,%1,%2,%3}, {%4,%5,%6,%7}, {%8,%9}, {%0,%1,%2,%3};"
        : "+f"(d[0]), "+f"(d[1]), "+f"(d[2]), "+f"(d[3])
        : "r"(a[0]), "r"(a[1]), "r"(a[2]), "r"(a[3]), "r"(b0), "r"(b1));
}

// Stage weight matrix W [Kf][Nf] row-major -> sW[n][k] transposed, tf32-rounded,
// zero-padding the accessed window [NT8 n][KT8 k].
__device__ __forceinline__ void stage_w(float* sW, const float* __restrict__ g,
                                        int Kf, int Nf, int KT8, int NT8, int t) {
    for (int i = t; i < KT8 * NT8; i += TPB) {
        int n = i % NT8;
        int k = i / NT8;
        float v = (k < Kf && n < Nf) ? g[k * Nf + n] : 0.f;
        sW[n * S + k] = cvt_tf32(v);
    }
}

// Stage [N,32] input rows block0..block0+255 into sA cols 0..31 (tf32-rounded).
__device__ __forceinline__ void stage_in(float* sA, const float* __restrict__ g,
                                         int block0, int t) {
    for (int i = t; i < PTS * 8; i += TPB) {
        int p  = i >> 3;
        int c4 = (i & 7) << 2;
        float4 v = *(const float4*)(g + (size_t)(block0 + p) * 32 + c4);
        float4 o = make_float4(cvt_tf32(v.x), cvt_tf32(v.y), cvt_tf32(v.z), cvt_tf32(v.w));
        *(float4*)(sA + p * S + c4) = o;
    }
}

// One layer for one warp: A = sAw [32 x 8*KT], B^T staged in sW [8*NT n][8*KT k].
// acc[mt*NT + nt][4], fp32.
template <int KT, int NT>
__device__ __forceinline__ void mma_layer(const float* __restrict__ sAw,
                                          const float* __restrict__ sW,
                                          int g, int cp, float (*acc)[4]) {
#pragma unroll
    for (int i = 0; i < 2 * NT; i++)
#pragma unroll
        for (int q = 0; q < 4; q++) acc[i][q] = 0.f;

#pragma unroll
    for (int kt = 0; kt < KT; kt++) {
        const int k0 = kt * 8;
        uint32_t a[2][4];
#pragma unroll
        for (int mt = 0; mt < 2; mt++) {
            const float* base = sAw + (mt * 16 + g) * S + k0 + cp;
            a[mt][0] = __float_as_uint(base[0]);
            a[mt][1] = __float_as_uint(base[8 * S]);
            a[mt][2] = __float_as_uint(base[4]);
            a[mt][3] = __float_as_uint(base[8 * S + 4]);
        }
#pragma unroll
        for (int nt = 0; nt < NT; nt++) {
            const float* wb = sW + (nt * 8 + g) * S + k0 + cp;
            uint32_t b0 = __float_as_uint(wb[0]);
            uint32_t b1 = __float_as_uint(wb[4]);
            mma8(acc[0 * NT + nt], a[0], b0, b1);
            mma8(acc[1 * NT + nt], a[1], b0, b1);
        }
    }
}

// ReLU + tf32-round + store D fragments back to sAw cols [0, 8*NT)
template <int NT>
__device__ __forceinline__ void store_relu(float* sAw, int g, int cp, float (*acc)[4]) {
#pragma unroll
    for (int mt = 0; mt < 2; mt++)
#pragma unroll
        for (int nt = 0; nt < NT; nt++)
#pragma unroll
            for (int h = 0; h < 2; h++) {
                int r = mt * 16 + g + 8 * h;
                float v0 = cvt_tf32(fmaxf(acc[mt * NT + nt][2 * h + 0], 0.f));
                float v1 = cvt_tf32(fmaxf(acc[mt * NT + nt][2 * h + 1], 0.f));
                *(float2*)(sAw + r * S + nt * 8 + 2 * cp) = make_float2(v0, v1);
            }
}

__global__ __launch_bounds__(TPB, 2)
void RadianceFieldGrid_kernel(const float* __restrict__ x,
                              const float* __restrict__ d,
                              const float* __restrict__ Ws0,
                              const float* __restrict__ Ws1,
                              const float* __restrict__ Ws2,
                              const float* __restrict__ Wc0,
                              const float* __restrict__ Wc1,
                              const float* __restrict__ Wc2,
                              const float* __restrict__ Wc3,
                              float* __restrict__ out, int N) {
    extern __shared__ float sm[];
    float* sA = sm;
    float* sW = sm + SA_FLOATS;

    const int t      = threadIdx.x;
    const int lane   = t & 31;
    const int w      = t >> 5;
    const int g      = lane >> 2;   // groupID (row within frag)
    const int cp     = lane & 3;    // threadID_in_group (col within frag)
    const int block0 = blockIdx.x * PTS;
    float* sAw = sA + w * 32 * S;   // this warp's 32 points

    float acc[16][4];

    // ---- stage x + Ws0 ----
    stage_in(sA, x, block0, t);
    stage_w(sW, Ws0, 32, 64, 32, 64, t);
    __syncthreads();

    // ---- sigma L0: K=32 -> N=64, relu ----
    mma_layer<4, 8>(sAw, sW, g, cp, acc);
    __syncwarp();
    store_relu<8>(sAw, g, cp, acc);
    __syncthreads();
    stage_w(sW, Ws1, 64, 64, 64, 64, t);
    __syncthreads();

    // ---- sigma L1: 64 -> 64, relu ----
    mma_layer<8, 8>(sAw, sW, g, cp, acc);
    __syncwarp();
    store_relu<8>(sAw, g, cp, acc);
    __syncthreads();
    stage_w(sW, Ws2, 64, 16, 64, 16, t);
    __syncthreads();

    // ---- sigma L2: 64 -> 16, relu. col0 = sigma -> gmem; cols1..15 = geo -> sA cols 32..46 ----
    mma_layer<8, 2>(sAw, sW, g, cp, acc);
    __syncwarp();
    {
#pragma unroll
        for (int mt = 0; mt < 2; mt++)
#pragma unroll
            for (int nt = 0; nt < 2; nt++)
#pragma unroll
                for (int q = 0; q < 4; q++) {
                    int r   = mt * 16 + g + 8 * (q >> 1);
                    int col = nt * 8 + 2 * cp + (q & 1);
                    float v = fmaxf(acc[mt * 2 + nt][q], 0.f);
                    if (col == 0) {
                        out[(size_t)3 * N + block0 + w * 32 + r] = v;
                    } else {
                        sAw[r * S + 31 + col] = cvt_tf32(v);   // geo j=col-1 -> col 32+(col-1)
                    }
                }
    }
    __syncthreads();
    // d into cols 0..31 (CTA-wide); Wc0 staged with k=47 zero-padded
    stage_in(sA, d, block0, t);
    stage_w(sW, Wc0, 47, 64, 48, 64, t);
    __syncthreads();

    // ---- color L0: K=48(47+pad) -> 64, relu ----
    mma_layer<6, 8>(sAw, sW, g, cp, acc);
    __syncwarp();
    store_relu<8>(sAw, g, cp, acc);
    __syncthreads();
    stage_w(sW, Wc1, 64, 64, 64, 64, t);
    __syncthreads();

    // ---- color L1: 64 -> 64, relu ----
    mma_layer<8, 8>(sAw, sW, g, cp, acc);
    __syncwarp();
    store_relu<8>(sAw, g, cp, acc);
    __syncthreads();
    stage_w(sW, Wc2, 64, 64, 64, 64, t);
    __syncthreads();

    // ---- color L2: 64 -> 64, relu ----
    mma_layer<8, 8>(sAw, sW, g, cp, acc);
    __syncwarp();
    store_relu<8>(sAw, g, cp, acc);
    __syncthreads();
    stage_w(sW, Wc3, 64, 3, 64, 8, t);
    __syncthreads();

    // ---- color L3: 64 -> 3, sigmoid, store ----
    mma_layer<8, 1>(sAw, sW, g, cp, acc);
#pragma unroll
    for (int mt = 0; mt < 2; mt++)
#pragma unroll
        for (int q = 0; q < 4; q++) {
            int col = 2 * cp + (q & 1);
            if (col < 3) {
                int r = mt * 16 + g + 8 * (q >> 1);
                int p = block0 + w * 32 + r;
                float v = acc[mt * 1 + 0][q];
                out[(size_t)p * 3 + col] = 1.f / (1.f + __expf(-v));
            }
        }
}

extern "C" void kernel_launch(void* const* d_in, const int* in_sizes, int n_in,
                              void* d_out, int out_size) {
    const float* x   = (const float*)d_in[0];
    const float* d   = (const float*)d_in[1];
    const float* Ws0 = (const float*)d_in[2];
    const float* Ws1 = (const float*)d_in[3];
    const float* Ws2 = (const float*)d_in[4];
    const float* Wc0 = (const float*)d_in[5];
    const float* Wc1 = (const float*)d_in[6];
    const float* Wc2 = (const float*)d_in[7];
    const float* Wc3 = (const float*)d_in[8];
    float* out = (float*)d_out;

    int N = in_sizes[0] / 32;       // x is [N, 32]
    int blocks = N / PTS;           // N = 2^20 -> 4096

    static int smem_set = 0;
    if (!smem_set) {
        cudaFuncSetAttribute(RadianceFieldGrid_kernel,
                             cudaFuncAttributeMaxDynamicSharedMemorySize, SMEM_BYTES);
        smem_set = 1;
    }
    RadianceFieldGrid_kernel<<<blocks, TPB, SMEM_BYTES>>>(x, d, Ws0, Ws1, Ws2,
                                                          Wc0, Wc1, Wc2, Wc3, out, N);
}

// round 5
// speedup vs baseline: 3.6635x; 1.5228x over previous
#include <cuda_runtime.h>
#include <cuda_bf16.h>
#include <cstdint>

#define TPB    512
#define WARPS  16
#define SSTR   68          // scratch col stride (floats); 68 mod 32 == 4 -> conflict-free frags

// fragment-linear weight buffer: per layer, float4 index (nt*KTP + p)*32 + lane
// float4 = (b0 kt=2p, b1 kt=2p, b0 kt=2p+1, b1 kt=2p+1)
#define OFF_S0 0
#define OFF_S1 2048
#define OFF_S2 6144
#define OFF_C0 7168
#define OFF_C1 10240
#define OFF_C2 14336
#define OFF_C3 18432
#define WTOT   18944       // floats
#define SCR_FLOATS (WARPS * 32 * SSTR)
#define SMEM_BYTES ((WTOT + SCR_FLOATS) * 4)

__device__ float wbuf[WTOT];

__device__ __forceinline__ float cvt_tf32(float x) {
    uint32_t u;
    asm("cvt.rna.tf32.f32 %0, %1;" : "=r"(u) : "f"(x));
    return __uint_as_float(u);
}

__device__ __forceinline__ void mma8(float* d, const uint32_t* a, uint32_t b0, uint32_t b1) {
    asm volatile(
        "mma.sync.aligned.m16n8k8.row.col.f32.tf32.tf32.f32 "
        "{%0,%1,%2,%3}, {%4,%5,%6,%7}, {%8,%9}, {%0,%1,%2,%3};"
        : "+f"(d[0]), "+f"(d[1]), "+f"(d[2]), "+f"(d[3])
        : "r"(a[0]), "r"(a[1]), "r"(a[2]), "r"(a[3]), "r"(b0), "r"(b1));
}

// ---------------- prep: weights -> fragment-linear tf32 ----------------
__global__ void prep_kernel(const float* __restrict__ Ws0, const float* __restrict__ Ws1,
                            const float* __restrict__ Ws2, const float* __restrict__ Wc0,
                            const float* __restrict__ Wc1, const float* __restrict__ Wc2,
                            const float* __restrict__ Wc3) {
    int i = blockIdx.x * blockDim.x + threadIdx.x;   // float4 index
    if (i >= WTOT / 4) return;
    const float* W; int Kf, Nf, KTP, off4;
    if      (i < 512)  { W = Ws0; Kf = 32; Nf = 64; KTP = 2; off4 = 0;    }
    else if (i < 1536) { W = Ws1; Kf = 64; Nf = 64; KTP = 4; off4 = 512;  }
    else if (i < 1792) { W = Ws2; Kf = 64; Nf = 16; KTP = 4; off4 = 1536; }
    else if (i < 2560) { W = Wc0; Kf = 47; Nf = 64; KTP = 3; off4 = 1792; }
    else if (i < 3584) { W = Wc1; Kf = 64; Nf = 64; KTP = 4; off4 = 2560; }
    else if (i < 4608) { W = Wc2; Kf = 64; Nf = 64; KTP = 4; off4 = 3584; }
    else               { W = Wc3; Kf = 64; Nf = 3;  KTP = 4; off4 = 4608; }
    int q = i - off4;
    int lane = q & 31, t2 = q >> 5;
    int p = t2 % KTP, nt = t2 / KTP;
    int g = lane >> 2, cp = lane & 3;
    int n = nt * 8 + g, ke = p * 16 + cp;
    float4 v;
    v.x = (ke      < Kf && n < Nf) ? cvt_tf32(W[(ke)      * Nf + n]) : 0.f;
    v.y = (ke + 4  < Kf && n < Nf) ? cvt_tf32(W[(ke + 4)  * Nf + n]) : 0.f;
    v.z = (ke + 8  < Kf && n < Nf) ? cvt_tf32(W[(ke + 8)  * Nf + n]) : 0.f;
    v.w = (ke + 12 < Kf && n < Nf) ? cvt_tf32(W[(ke + 12) * Nf + n]) : 0.f;
    ((float4*)wbuf)[i] = v;
}

// ---------------- main kernel helpers ----------------

// One layer for one warp. A read per k-tile from the warp's scratch slice;
// B fragments via LDS.128 from fragment-linear smem weights.
template <int KTP, int NT>
__device__ __forceinline__ void mma_frag(const float* __restrict__ sc,
                                         const float* __restrict__ swL,
                                         int g, int cp, int lane, float (*acc)[4]) {
#pragma unroll
    for (int i = 0; i < 2 * NT; i++)
#pragma unroll
        for (int q = 0; q < 4; q++) acc[i][q] = 0.f;

#pragma unroll
    for (int p = 0; p < KTP; p++) {
        uint32_t aE[2][4], aO[2][4];
#pragma unroll
        for (int mt = 0; mt < 2; mt++) {
            const float* b = sc + (mt * 16 + g) * SSTR + p * 16 + cp;
            aE[mt][0] = __float_as_uint(b[0]);
            aE[mt][1] = __float_as_uint(b[8 * SSTR]);
            aE[mt][2] = __float_as_uint(b[4]);
            aE[mt][3] = __float_as_uint(b[8 * SSTR + 4]);
            aO[mt][0] = __float_as_uint(b[8]);
            aO[mt][1] = __float_as_uint(b[8 * SSTR + 8]);
            aO[mt][2] = __float_as_uint(b[12]);
            aO[mt][3] = __float_as_uint(b[8 * SSTR + 12]);
        }
#pragma unroll
        for (int nt = 0; nt < NT; nt++) {
            float4 wv = ((const float4*)swL)[(nt * KTP + p) * 32 + lane];
            uint32_t b0e = __float_as_uint(wv.x), b1e = __float_as_uint(wv.y);
            uint32_t b0o = __float_as_uint(wv.z), b1o = __float_as_uint(wv.w);
            mma8(acc[0 * NT + nt], aE[0], b0e, b1e);
            mma8(acc[1 * NT + nt], aE[1], b0e, b1e);
            mma8(acc[0 * NT + nt], aO[0], b0o, b1o);
            mma8(acc[1 * NT + nt], aO[1], b0o, b1o);
        }
    }
}

template <int NT>
__device__ __forceinline__ void wb_relu(float* sc, int g, int cp, float (*acc)[4]) {
#pragma unroll
    for (int mt = 0; mt < 2; mt++)
#pragma unroll
        for (int nt = 0; nt < NT; nt++)
#pragma unroll
            for (int h = 0; h < 2; h++) {
                int row = mt * 16 + g + 8 * h;
                float v0 = cvt_tf32(fmaxf(acc[mt * NT + nt][2 * h + 0], 0.f));
                float v1 = cvt_tf32(fmaxf(acc[mt * NT + nt][2 * h + 1], 0.f));
                *(float2*)(sc + row * SSTR + nt * 8 + 2 * cp) = make_float2(v0, v1);
            }
}

// Stage 32 points x 32 cols of [N,32] gmem into warp scratch cols 0..31 (tf32-rounded)
__device__ __forceinline__ void stage32(float* sc, const float* __restrict__ gsrc,
                                        int p0, int lane) {
#pragma unroll
    for (int j = lane; j < 256; j += 32) {
        int p  = j >> 3;
        int c4 = (j & 7) << 2;
        float4 v = *(const float4*)(gsrc + (size_t)(p0 + p) * 32 + c4);
        float4 o = make_float4(cvt_tf32(v.x), cvt_tf32(v.y), cvt_tf32(v.z), cvt_tf32(v.w));
        *(float4*)(sc + p * SSTR + c4) = o;
    }
}

__global__ __launch_bounds__(TPB, 1)
void RadianceFieldGrid_kernel(const float* __restrict__ x,
                              const float* __restrict__ din,
                              float* __restrict__ out, int N) {
    extern __shared__ float sm[];
    float* sW   = sm;
    float* sScr = sm + WTOT;

    const int t    = threadIdx.x;
    const int lane = t & 31;
    const int w    = t >> 5;
    const int g    = lane >> 2;
    const int cp   = lane & 3;
    const int p0   = blockIdx.x * TPB + w * 32;  // this warp's first point
    float* sc = sScr + w * 32 * SSTR;

    // one-time weight copy into smem (fragment-linear), single CTA-wide sync
    for (int i = t; i < WTOT / 4; i += TPB)
        ((float4*)sW)[i] = ((const float4*)wbuf)[i];
    __syncthreads();

    float acc[16][4];

    // ---- stage x ----
    stage32(sc, x, p0, lane);
    __syncwarp();

    // ---- sigma L0: 32 -> 64 ----
    mma_frag<2, 8>(sc, sW + OFF_S0, g, cp, lane, acc);
    __syncwarp();
    wb_relu<8>(sc, g, cp, acc);
    __syncwarp();

    // ---- sigma L1: 64 -> 64 ----
    mma_frag<4, 8>(sc, sW + OFF_S1, g, cp, lane, acc);
    __syncwarp();
    wb_relu<8>(sc, g, cp, acc);
    __syncwarp();

    // ---- sigma L2: 64 -> 16 ----
    mma_frag<4, 2>(sc, sW + OFF_S2, g, cp, lane, acc);
    __syncwarp();
    // sigma (col 0) -> gmem; geo (cols 1..15) -> scratch cols 32..46; col 47 = 0
#pragma unroll
    for (int mt = 0; mt < 2; mt++)
#pragma unroll
        for (int nt = 0; nt < 2; nt++)
#pragma unroll
            for (int q = 0; q < 4; q++) {
                int c   = nt * 8 + 2 * cp + (q & 1);
                int row = mt * 16 + g + 8 * (q >> 1);
                float v = fmaxf(acc[mt * 2 + nt][q], 0.f);
                if (c == 0) out[(size_t)3 * N + p0 + row] = v;
                else        sc[row * SSTR + 31 + c] = cvt_tf32(v);
            }
    if (cp == 0) {
        sc[(g)      * SSTR + 47] = 0.f;
        sc[(g + 8)  * SSTR + 47] = 0.f;
        sc[(g + 16) * SSTR + 47] = 0.f;
        sc[(g + 24) * SSTR + 47] = 0.f;
    }
    __syncwarp();

    // ---- stage d into cols 0..31 (geo stays in 32..47) ----
    stage32(sc, din, p0, lane);
    __syncwarp();

    // ---- color L0: 48(47+pad) -> 64 ----
    mma_frag<3, 8>(sc, sW + OFF_C0, g, cp, lane, acc);
    __syncwarp();
    wb_relu<8>(sc, g, cp, acc);
    __syncwarp();

    // ---- color L1: 64 -> 64 ----
    mma_frag<4, 8>(sc, sW + OFF_C1, g, cp, lane, acc);
    __syncwarp();
    wb_relu<8>(sc, g, cp, acc);
    __syncwarp();

    // ---- color L2: 64 -> 64 ----
    mma_frag<4, 8>(sc, sW + OFF_C2, g, cp, lane, acc);
    __syncwarp();
    wb_relu<8>(sc, g, cp, acc);
    __syncwarp();

    // ---- color L3: 64 -> 3 (rows 3..7 of B are zero-padded) ----
    mma_frag<4, 1>(sc, sW + OFF_C3, g, cp, lane, acc);
#pragma unroll
    for (int mt = 0; mt < 2; mt++)
#pragma unroll
        for (int q = 0; q < 4; q++) {
            int c = 2 * cp + (q & 1);
            if (c < 3) {
                int row = mt * 16 + g + 8 * (q >> 1);
                float v = acc[mt][q];
                out[(size_t)(p0 + row) * 3 + c] = 1.f / (1.f + __expf(-v));
            }
        }
}

extern "C" void kernel_launch(void* const* d_in, const int* in_sizes, int n_in,
                              void* d_out, int out_size) {
    const float* x   = (const float*)d_in[0];
    const float* din = (const float*)d_in[1];
    const float* Ws0 = (const float*)d_in[2];
    const float* Ws1 = (const float*)d_in[3];
    const float* Ws2 = (const float*)d_in[4];
    const float* Wc0 = (const float*)d_in[5];
    const float* Wc1 = (const float*)d_in[6];
    const float* Wc2 = (const float*)d_in[7];
    const float* Wc3 = (const float*)d_in[8];
    float* out = (float*)d_out;

    int N = in_sizes[0] / 32;   // x is [N, 32]

    static int smem_set = 0;
    if (!smem_set) {
        cudaFuncSetAttribute(RadianceFieldGrid_kernel,
                             cudaFuncAttributeMaxDynamicSharedMemorySize, SMEM_BYTES);
        smem_set = 1;
    }

    prep_kernel<<<(WTOT / 4 + 255) / 256, 256>>>(Ws0, Ws1, Ws2, Wc0, Wc1, Wc2, Wc3);
    RadianceFieldGrid_kernel<<<N / TPB, TPB, SMEM_BYTES>>>(x, din, out, N);
}

// round 6
// speedup vs baseline: 8.9502x; 2.4431x over previous
#include <cuda_runtime.h>
#include <cuda_fp16.h>
#include <cstdint>

#define TPB 256

// ---- fragment-linear fp16 weight buffer ----
// Per (layer, nt, kh, lane): uint4 = (b0 kt=2kh, b1 kt=2kh, b0 kt=2kh+1, b1 kt=2kh+1)
// where b0 = f16x2 (W[k=16kt+2cp][n], W[k=16kt+2cp+1][n]), b1 = k+8, n = nt*8+g.
// Offsets in uint4 units:
#define OFF_S0 0        // K=32 (KH=1), N=64: 8*1*32  = 256
#define OFF_S1 256      // K=64 (KH=2), N=64: 8*2*32  = 512
#define OFF_S2 768      // K=64, N=16: 2*2*32 = 128
#define OFF_C0 896      // K=48 permuted (KH=2), N=64: 512
#define OFF_C1 1408     // 512
#define OFF_C2 1920     // 512
#define OFF_C3 2432     // K=64, N=8: 1*2*32 = 64
#define WU4    2496

__device__ uint4 wbuf[WU4];

__device__ __forceinline__ uint32_t h2pack(float a, float b) {
    __half2 h = __floats2half2_rn(a, b);
    return *(uint32_t*)&h;
}
__device__ __forceinline__ uint32_t h2relu(float a, float b) {
    return h2pack(fmaxf(a, 0.f), fmaxf(b, 0.f));
}

__device__ __forceinline__ void mma16(float* d, const uint32_t* a, uint32_t b0, uint32_t b1) {
    asm volatile(
        "mma.sync.aligned.m16n8k16.row.col.f32.f16.f16.f32 "
        "{%0,%1,%2,%3}, {%4,%5,%6,%7}, {%8,%9}, {%0,%1,%2,%3};"
        : "+f"(d[0]), "+f"(d[1]), "+f"(d[2]), "+f"(d[3])
        : "r"(a[0]), "r"(a[1]), "r"(a[2]), "r"(a[3]), "r"(b0), "r"(b1));
}

// ---------------- prep: weights -> fragment-linear fp16 ----------------
__device__ __forceinline__ float wfetch(const float* W, int Nf, int n, int kk, bool c0) {
    if (n >= Nf) return 0.f;
    int src;
    if (c0) {                       // concat layout: [d 0..31, zero@32, geo@33..47]
        if (kk < 32) src = kk;
        else if (kk == 32) return 0.f;
        else src = kk - 1;          // geo j at pos 33+j -> Wc0 row 32+j
        if (src >= 47) return 0.f;
    } else {
        src = kk;
    }
    return W[src * Nf + n];
}

__global__ void prep_kernel(const float* __restrict__ Ws0, const float* __restrict__ Ws1,
                            const float* __restrict__ Ws2, const float* __restrict__ Wc0,
                            const float* __restrict__ Wc1, const float* __restrict__ Wc2,
                            const float* __restrict__ Wc3) {
    int i = blockIdx.x * blockDim.x + threadIdx.x;
    if (i >= WU4) return;
    const float* W; int Kf, Nf, KH, q; bool c0 = false;
    if      (i < 256)  { W = Ws0; Kf = 32; Nf = 64; KH = 1; q = i;        }
    else if (i < 768)  { W = Ws1; Kf = 64; Nf = 64; KH = 2; q = i - 256;  }
    else if (i < 896)  { W = Ws2; Kf = 64; Nf = 16; KH = 2; q = i - 768;  }
    else if (i < 1408) { W = Wc0; Kf = 48; Nf = 64; KH = 2; q = i - 896; c0 = true; }
    else if (i < 1920) { W = Wc1; Kf = 64; Nf = 64; KH = 2; q = i - 1408; }
    else if (i < 2432) { W = Wc2; Kf = 64; Nf = 64; KH = 2; q = i - 1920; }
    else               { W = Wc3; Kf = 64; Nf = 3;  KH = 2; q = i - 2432; }

    int lane = q & 31, t2 = q >> 5;
    int kh = t2 % KH, nt = t2 / KH;
    int g = lane >> 2, cp = lane & 3;
    int n = nt * 8 + g;

    auto pw = [&](int kk) -> float {
        return (kk < Kf) ? wfetch(W, Nf, n, kk, c0) : 0.f;
    };
    int k0 = 16 * (2 * kh) + 2 * cp;
    int k1 = 16 * (2 * kh + 1) + 2 * cp;
    uint4 v;
    v.x = h2pack(pw(k0),     pw(k0 + 1));
    v.y = h2pack(pw(k0 + 8), pw(k0 + 9));
    v.z = h2pack(pw(k1),     pw(k1 + 1));
    v.w = h2pack(pw(k1 + 8), pw(k1 + 9));
    wbuf[i] = v;
}

// ---------------- main kernel ----------------

// aR[mt][kt][0..3]: A frags for up to K=64. acc[mt*NT+nt][0..3].
template <int KT, int NT>
__device__ __forceinline__ void layer_mma(const uint32_t (*aR)[4][4], const uint4* __restrict__ swL,
                                          int lane, float (*acc)[4]) {
    constexpr int KH = (KT + 1) / 2;
#pragma unroll
    for (int i = 0; i < 2 * NT; i++)
#pragma unroll
        for (int qq = 0; qq < 4; qq++) acc[i][qq] = 0.f;
#pragma unroll
    for (int nt = 0; nt < NT; nt++) {
#pragma unroll
        for (int kh = 0; kh < KH; kh++) {
            uint4 wv = swL[(nt * KH + kh) * 32 + lane];
#pragma unroll
            for (int mt = 0; mt < 2; mt++) {
                mma16(acc[mt * NT + nt], aR[mt][2 * kh], wv.x, wv.y);
                if (2 * kh + 1 < KT)
                    mma16(acc[mt * NT + nt], aR[mt][2 * kh + 1], wv.z, wv.w);
            }
        }
    }
}

// D(f32, 8 n-tiles) -> A(f16, 4 k-tiles) with fused ReLU. Zero data movement.
__device__ __forceinline__ void cvt_relu8(const float (*acc)[4], uint32_t (*aR)[4][4]) {
#pragma unroll
    for (int mt = 0; mt < 2; mt++)
#pragma unroll
        for (int nt = 0; nt < 8; nt++) {
            int kt = nt >> 1, hi = (nt & 1) * 2;
            const float* dd = acc[mt * 8 + nt];
            aR[mt][kt][hi + 0] = h2relu(dd[0], dd[1]);
            aR[mt][kt][hi + 1] = h2relu(dd[2], dd[3]);
        }
}

// Load x/d [N,32] rows into A frags kt=0,1 (fp16).
__device__ __forceinline__ void load_in(uint32_t (*aR)[4][4], const float* __restrict__ gsrc,
                                        int p0, int g, int cp) {
#pragma unroll
    for (int mt = 0; mt < 2; mt++)
#pragma unroll
        for (int kt = 0; kt < 2; kt++) {
            const float* ra = gsrc + (size_t)(p0 + mt * 16 + g) * 32 + 2 * cp + 16 * kt;
            const float* rb = ra + 8 * 32;   // row +8
            float2 v0 = *(const float2*)(ra);
            float2 v1 = *(const float2*)(rb);
            float2 v2 = *(const float2*)(ra + 8);
            float2 v3 = *(const float2*)(rb + 8);
            aR[mt][kt][0] = h2pack(v0.x, v0.y);
            aR[mt][kt][1] = h2pack(v1.x, v1.y);
            aR[mt][kt][2] = h2pack(v2.x, v2.y);
            aR[mt][kt][3] = h2pack(v3.x, v3.y);
        }
}

__global__ __launch_bounds__(TPB, 2)
void RadianceFieldGrid_kernel(const float* __restrict__ x,
                              const float* __restrict__ din,
                              float* __restrict__ out, int N) {
    __shared__ uint4 sW[WU4];   // 39.9 KB

    const int t    = threadIdx.x;
    const int lane = t & 31;
    const int w    = t >> 5;
    const int g    = lane >> 2;
    const int cp   = lane & 3;
    const int p0   = blockIdx.x * TPB + w * 32;

    for (int i = t; i < WU4; i += TPB) sW[i] = wbuf[i];
    __syncthreads();

    uint32_t aR[2][4][4];
    float acc[16][4];

    // ---- sigma net ----
    load_in(aR, x, p0, g, cp);
    layer_mma<2, 8>(aR, sW + OFF_S0, lane, acc);
    cvt_relu8(acc, aR);
    layer_mma<4, 8>(aR, sW + OFF_S1, lane, acc);
    cvt_relu8(acc, aR);
    layer_mma<4, 2>(aR, sW + OFF_S2, lane, acc);   // acc[mt*2+nt]

    // sigma = relu(col 0) -> out[3N + p]
    if (cp == 0) {
#pragma unroll
        for (int mt = 0; mt < 2; mt++) {
            out[(size_t)3 * N + p0 + mt * 16 + g]     = fmaxf(acc[mt * 2][0], 0.f);
            out[(size_t)3 * N + p0 + mt * 16 + g + 8] = fmaxf(acc[mt * 2][2], 0.f);
        }
    }

    // color A k-tile 2 = relu(L2 D-frags); pos 32 (sigma) hits zero weight row
#pragma unroll
    for (int mt = 0; mt < 2; mt++) {
        const float* d0 = acc[mt * 2 + 0];
        const float* d1 = acc[mt * 2 + 1];
        aR[mt][2][0] = h2relu(d0[0], d0[1]);
        aR[mt][2][1] = h2relu(d0[2], d0[3]);
        aR[mt][2][2] = h2relu(d1[0], d1[1]);
        aR[mt][2][3] = h2relu(d1[2], d1[3]);
    }
    load_in(aR, din, p0, g, cp);   // k-tiles 0,1 = d

    // ---- color net ----
    layer_mma<3, 8>(aR, sW + OFF_C0, lane, acc);
    cvt_relu8(acc, aR);
    layer_mma<4, 8>(aR, sW + OFF_C1, lane, acc);
    cvt_relu8(acc, aR);
    layer_mma<4, 8>(aR, sW + OFF_C2, lane, acc);
    cvt_relu8(acc, aR);
    layer_mma<4, 1>(aR, sW + OFF_C3, lane, acc);   // acc[mt]

    // sigmoid + store color (cols 0..2 of the single n-tile)
#pragma unroll
    for (int mt = 0; mt < 2; mt++)
#pragma unroll
        for (int qq = 0; qq < 4; qq++) {
            int c = 2 * cp + (qq & 1);
            if (c < 3) {
                int row = mt * 16 + g + 8 * (qq >> 1);
                float v = acc[mt][qq];
                out[(size_t)(p0 + row) * 3 + c] = 1.f / (1.f + __expf(-v));
            }
        }
}

extern "C" void kernel_launch(void* const* d_in, const int* in_sizes, int n_in,
                              void* d_out, int out_size) {
    const float* x   = (const float*)d_in[0];
    const float* din = (const float*)d_in[1];
    const float* Ws0 = (const float*)d_in[2];
    const float* Ws1 = (const float*)d_in[3];
    const float* Ws2 = (const float*)d_in[4];
    const float* Wc0 = (const float*)d_in[5];
    const float* Wc1 = (const float*)d_in[6];
    const float* Wc2 = (const float*)d_in[7];
    const float* Wc3 = (const float*)d_in[8];
    float* out = (float*)d_out;

    int N = in_sizes[0] / 32;   // x is [N, 32]

    prep_kernel<<<(WU4 + 255) / 256, 256>>>(Ws0, Ws1, Ws2, Wc0, Wc1, Wc2, Wc3);
    RadianceFieldGrid_kernel<<<N / TPB, TPB>>>(x, din, out, N);
}

// round 8
// speedup vs baseline: 9.2310x; 1.0314x over previous
#include <cuda_runtime.h>
#include <cuda_fp16.h>
#include <cstdint>

#define TPB 256

// ---- fragment-linear fp16 weight buffer ----
// Per (layer, nt, kh, lane): uint4 = (b0 kt=2kh, b1 kt=2kh, b0 kt=2kh+1, b1 kt=2kh+1)
// where b0 = f16x2 (W[k=16kt+2cp][n], W[k=16kt+2cp+1][n]), b1 = k+8, n = nt*8+g.
// Offsets in uint4 units:
#define OFF_S0 0        // K=32 (KH=1), N=64: 8*1*32  = 256
#define OFF_S1 256      // K=64 (KH=2), N=64: 8*2*32  = 512
#define OFF_S2 768      // K=64, N=16: 2*2*32 = 128
#define OFF_C0 896      // K=48 permuted (KH=2), N=64: 512
#define OFF_C1 1408     // 512
#define OFF_C2 1920     // 512
#define OFF_C3 2432     // K=64, N=8: 1*2*32 = 64
#define WU4    2496

__device__ uint4 wbuf[WU4];

__device__ __forceinline__ uint32_t h2pack(float a, float b) {
    __half2 h = __floats2half2_rn(a, b);
    return *(uint32_t*)&h;
}
// pack then relu in fp16 (1 F2FP + 1 HMNMX2 instead of 2 FMNMX + 1 F2FP)
__device__ __forceinline__ uint32_t h2relu(float a, float b) {
    __half2 h = __floats2half2_rn(a, b);
    h = __hmax2(h, __half2(__float2half_rn(0.f), __float2half_rn(0.f)));
    return *(uint32_t*)&h;
}

__device__ __forceinline__ void mma16(float* d, const uint32_t* a, uint32_t b0, uint32_t b1) {
    asm volatile(
        "mma.sync.aligned.m16n8k16.row.col.f32.f16.f16.f32 "
        "{%0,%1,%2,%3}, {%4,%5,%6,%7}, {%8,%9}, {%0,%1,%2,%3};"
        : "+f"(d[0]), "+f"(d[1]), "+f"(d[2]), "+f"(d[3])
        : "r"(a[0]), "r"(a[1]), "r"(a[2]), "r"(a[3]), "r"(b0), "r"(b1));
}

// ---------------- prep: weights -> fragment-linear fp16 ----------------
__device__ __forceinline__ float wfetch(const float* W, int Nf, int n, int kk, bool c0) {
    if (n >= Nf) return 0.f;
    int src;
    if (c0) {                       // concat layout: [d 0..31, zero@32, geo@33..47]
        if (kk < 32) src = kk;
        else if (kk == 32) return 0.f;
        else src = kk - 1;          // geo j at pos 33+j -> Wc0 row 32+j
        if (src >= 47) return 0.f;
    } else {
        src = kk;
    }
    return W[src * Nf + n];
}

__global__ void prep_kernel(const float* __restrict__ Ws0, const float* __restrict__ Ws1,
                            const float* __restrict__ Ws2, const float* __restrict__ Wc0,
                            const float* __restrict__ Wc1, const float* __restrict__ Wc2,
                            const float* __restrict__ Wc3) {
    int i = blockIdx.x * blockDim.x + threadIdx.x;
    if (i >= WU4) return;
    const float* W; int Kf, Nf, KH, q; bool c0 = false;
    if      (i < 256)  { W = Ws0; Kf = 32; Nf = 64; KH = 1; q = i;        }
    else if (i < 768)  { W = Ws1; Kf = 64; Nf = 64; KH = 2; q = i - 256;  }
    else if (i < 896)  { W = Ws2; Kf = 64; Nf = 16; KH = 2; q = i - 768;  }
    else if (i < 1408) { W = Wc0; Kf = 48; Nf = 64; KH = 2; q = i - 896; c0 = true; }
    else if (i < 1920) { W = Wc1; Kf = 64; Nf = 64; KH = 2; q = i - 1408; }
    else if (i < 2432) { W = Wc2; Kf = 64; Nf = 64; KH = 2; q = i - 1920; }
    else               { W = Wc3; Kf = 64; Nf = 3;  KH = 2; q = i - 2432; }

    int lane = q & 31, t2 = q >> 5;
    int kh = t2 % KH, nt = t2 / KH;
    int g = lane >> 2, cp = lane & 3;
    int n = nt * 8 + g;

    auto pw = [&](int kk) -> float {
        return (kk < Kf) ? wfetch(W, Nf, n, kk, c0) : 0.f;
    };
    int k0 = 16 * (2 * kh) + 2 * cp;
    int k1 = 16 * (2 * kh + 1) + 2 * cp;
    uint4 v;
    v.x = h2pack(pw(k0),     pw(k0 + 1));
    v.y = h2pack(pw(k0 + 8), pw(k0 + 9));
    v.z = h2pack(pw(k1),     pw(k1 + 1));
    v.w = h2pack(pw(k1 + 8), pw(k1 + 9));
    wbuf[i] = v;
}

// ---------------- main kernel ----------------

// aR[mt][kt][0..3]: A frags for up to K=64. acc[mt*NT+nt][0..3].
// ILP-oriented schedule: for each kh, prefetch B frags for a 4-wide nt group,
// then sweep kt-even across all (nt, mt) pairs, then kt-odd. Dependent MMAs
// on the same accumulator are spaced by >= 8 independent MMAs.
template <int KT, int NT>
__device__ __forceinline__ void layer_mma(const uint32_t (*aR)[4][4], const uint4* __restrict__ swL,
                                          int lane, float (*acc)[4]) {
    constexpr int KH = (KT + 1) / 2;
    constexpr int NG = (NT < 4) ? NT : 4;          // nt group width
#pragma unroll
    for (int i = 0; i < 2 * NT; i++)
#pragma unroll
        for (int qq = 0; qq < 4; qq++) acc[i][qq] = 0.f;

#pragma unroll
    for (int kh = 0; kh < KH; kh++) {
#pragma unroll
        for (int h = 0; h < NT / NG; h++) {
            uint4 wv[NG];
#pragma unroll
            for (int j = 0; j < NG; j++)
                wv[j] = swL[((h * NG + j) * KH + kh) * 32 + lane];
            // kt even pass: all independent
#pragma unroll
            for (int j = 0; j < NG; j++)
#pragma unroll
                for (int mt = 0; mt < 2; mt++)
                    mma16(acc[mt * NT + h * NG + j], aR[mt][2 * kh], wv[j].x, wv[j].y);
            // kt odd pass
            if (2 * kh + 1 < KT) {
#pragma unroll
                for (int j = 0; j < NG; j++)
#pragma unroll
                    for (int mt = 0; mt < 2; mt++)
                        mma16(acc[mt * NT + h * NG + j], aR[mt][2 * kh + 1], wv[j].z, wv[j].w);
            }
        }
    }
}

// D(f32, 8 n-tiles) -> A(f16, 4 k-tiles) with fused ReLU. Zero data movement.
__device__ __forceinline__ void cvt_relu8(const float (*acc)[4], uint32_t (*aR)[4][4]) {
#pragma unroll
    for (int mt = 0; mt < 2; mt++)
#pragma unroll
        for (int nt = 0; nt < 8; nt++) {
            int kt = nt >> 1, hi = (nt & 1) * 2;
            const float* dd = acc[mt * 8 + nt];
            aR[mt][kt][hi + 0] = h2relu(dd[0], dd[1]);
            aR[mt][kt][hi + 1] = h2relu(dd[2], dd[3]);
        }
}

// Load x/d [N,32] rows into A frags kt=0,1 (fp16).
__device__ __forceinline__ void load_in(uint32_t (*aR)[4][4], const float* __restrict__ gsrc,
                                        int p0, int g, int cp) {
#pragma unroll
    for (int mt = 0; mt < 2; mt++)
#pragma unroll
        for (int kt = 0; kt < 2; kt++) {
            const float* ra = gsrc + (size_t)(p0 + mt * 16 + g) * 32 + 2 * cp + 16 * kt;
            const float* rb = ra + 8 * 32;   // row +8
            float2 v0 = *(const float2*)(ra);
            float2 v1 = *(const float2*)(rb);
            float2 v2 = *(const float2*)(ra + 8);
            float2 v3 = *(const float2*)(rb + 8);
            aR[mt][kt][0] = h2pack(v0.x, v0.y);
            aR[mt][kt][1] = h2pack(v1.x, v1.y);
            aR[mt][kt][2] = h2pack(v2.x, v2.y);
            aR[mt][kt][3] = h2pack(v3.x, v3.y);
        }
}

__global__ __launch_bounds__(TPB, 2)
void RadianceFieldGrid_kernel(const float* __restrict__ x,
                              const float* __restrict__ din,
                              float* __restrict__ out, int N) {
    __shared__ uint4 sW[WU4];   // 39.9 KB

    const int t    = threadIdx.x;
    const int lane = t & 31;
    const int w    = t >> 5;
    const int g    = lane >> 2;
    const int cp   = lane & 3;
    const int p0   = blockIdx.x * TPB + w * 32;

    for (int i = t; i < WU4; i += TPB) sW[i] = wbuf[i];
    __syncthreads();

    uint32_t aR[2][4][4];
    float acc[16][4];

    // ---- sigma net ----
    load_in(aR, x, p0, g, cp);
    layer_mma<2, 8>(aR, sW + OFF_S0, lane, acc);
    cvt_relu8(acc, aR);
    layer_mma<4, 8>(aR, sW + OFF_S1, lane, acc);
    cvt_relu8(acc, aR);
    layer_mma<4, 2>(aR, sW + OFF_S2, lane, acc);   // acc[mt*2+nt]

    // sigma = relu(col 0) -> out[3N + p]
    if (cp == 0) {
#pragma unroll
        for (int mt = 0; mt < 2; mt++) {
            out[(size_t)3 * N + p0 + mt * 16 + g]     = fmaxf(acc[mt * 2][0], 0.f);
            out[(size_t)3 * N + p0 + mt * 16 + g + 8] = fmaxf(acc[mt * 2][2], 0.f);
        }
    }

    // color A k-tile 2 = relu(L2 D-frags); pos 32 (sigma) hits zero weight row
#pragma unroll
    for (int mt = 0; mt < 2; mt++) {
        const float* d0 = acc[mt * 2 + 0];
        const float* d1 = acc[mt * 2 + 1];
        aR[mt][2][0] = h2relu(d0[0], d0[1]);
        aR[mt][2][1] = h2relu(d0[2], d0[3]);
        aR[mt][2][2] = h2relu(d1[0], d1[1]);
        aR[mt][2][3] = h2relu(d1[2], d1[3]);
    }
    load_in(aR, din, p0, g, cp);   // k-tiles 0,1 = d

    // ---- color net ----
    layer_mma<3, 8>(aR, sW + OFF_C0, lane, acc);
    cvt_relu8(acc, aR);
    layer_mma<4, 8>(aR, sW + OFF_C1, lane, acc);
    cvt_relu8(acc, aR);
    layer_mma<4, 8>(aR, sW + OFF_C2, lane, acc);
    cvt_relu8(acc, aR);
    layer_mma<4, 1>(aR, sW + OFF_C3, lane, acc);   // acc[mt]

    // sigmoid + store color (cols 0..2 of the single n-tile)
#pragma unroll
    for (int mt = 0; mt < 2; mt++)
#pragma unroll
        for (int qq = 0; qq < 4; qq++) {
            int c = 2 * cp + (qq & 1);
            if (c < 3) {
                int row = mt * 16 + g + 8 * (qq >> 1);
                float v = acc[mt][qq];
                out[(size_t)(p0 + row) * 3 + c] = 1.f / (1.f + __expf(-v));
            }
        }
}

extern "C" void kernel_launch(void* const* d_in, const int* in_sizes, int n_in,
                              void* d_out, int out_size) {
    const float* x   = (const float*)d_in[0];
    const float* din = (const float*)d_in[1];
    const float* Ws0 = (const float*)d_in[2];
    const float* Ws1 = (const float*)d_in[3];
    const float* Ws2 = (const float*)d_in[4];
    const float* Wc0 = (const float*)d_in[5];
    const float* Wc1 = (const float*)d_in[6];
    const float* Wc2 = (const float*)d_in[7];
    const float* Wc3 = (const float*)d_in[8];
    float* out = (float*)d_out;

    int N = in_sizes[0] / 32;   // x is [N, 32]

    prep_kernel<<<(WU4 + 255) / 256, 256>>>(Ws0, Ws1, Ws2, Wc0, Wc1, Wc2, Wc3);
    RadianceFieldGrid_kernel<<<N / TPB, TPB>>>(x, din, out, N);
}